// round 17
// baseline (speedup 1.0000x reference)
#include <cuda_runtime.h>
#include <cuda_bf16.h>
#include <math.h>
#include <stdint.h>

#define NROWS 65536
#define KC 256
#define DH 256
#define NKSZ ((size_t)NROWS * KC)
#define EPSV 1e-6f
#define SIGMA_HI_V 10000.0f
#define TARGET_Z 1.3219281f   /* log2(5)-1 */
#define TARGET_U 2.3219281f   /* log2(5)   */
#define INF_F __int_as_float(0x7f800000)
#define CAL_ITERS 64
#define NPART 512

// ---------------- scratch (device globals; no runtime allocation) ----------
__device__ float g_d[NKSZ];                 // 64MB distance matrix
__device__ uint4 g_mhi4[KC * 64];           // mu hi tf32-in-f32 (16B quads)
__device__ uint4 g_mlo4[KC * 64];           // mu lo tf32-in-f32
__device__ float g_m2[KC], g_ms[KC];
__device__ float g_relz[(size_t)NROWS * 5];
__device__ float g_rhoz[NROWS];
__device__ float g_sigz[NROWS];
__device__ float g_part1[NPART * 5 * KC];   // [cta][s][col]
__device__ float g_rhou[KC];
__device__ float g_sigu[KC];
__device__ float g_colsum[KC];

// ---------------- PTX helpers (baseline PTX only) ----------------------------
__device__ __forceinline__ uint32_t smem_u32(const void* p) {
    uint32_t a;
    asm("{ .reg .u64 t; cvta.to.shared.u64 t, %1; cvt.u32.u64 %0, t; }" : "=r"(a) : "l"(p));
    return a;
}

__device__ __forceinline__ uint32_t tf32u(float x) {
    uint32_t u;
    asm("cvt.rna.tf32.f32 %0, %1;" : "=r"(u) : "f"(x));
    return u;
}

__device__ __forceinline__ void ldmx4(uint32_t* r, uint32_t addr) {
    asm volatile("ldmatrix.sync.aligned.m8n8.x4.shared.b16 {%0,%1,%2,%3}, [%4];"
                 : "=r"(r[0]), "=r"(r[1]), "=r"(r[2]), "=r"(r[3]) : "r"(addr));
}

__device__ __forceinline__ void mma_tf32(float* d, const uint32_t* a, const uint32_t* b) {
    asm volatile(
        "mma.sync.aligned.m16n8k8.row.col.f32.tf32.tf32.f32 "
        "{%0,%1,%2,%3}, {%4,%5,%6,%7}, {%8,%9}, {%0,%1,%2,%3};"
        : "+f"(d[0]), "+f"(d[1]), "+f"(d[2]), "+f"(d[3])
        : "r"(a[0]), "r"(a[1]), "r"(a[2]), "r"(a[3]), "r"(b[0]), "r"(b[1]));
}

__device__ __forceinline__ void cpa16(uint32_t dst, const void* src) {
    asm volatile("cp.async.cg.shared.global [%0], [%1], 16;"
                 :: "r"(dst), "l"(__cvta_generic_to_global(src)));
}

// ---------------- K0: mu prep (warp per row; parallel) ------------------------
__global__ __launch_bounds__(256) void k_prep_mu(const float* __restrict__ mu) {
    int row = blockIdx.x * 8 + (threadIdx.x >> 5);
    int lane = threadIdx.x & 31;
    const float* r = mu + (size_t)row * DH + lane * 8;
    float m2 = 0.f, ms = 0.f;
#pragma unroll
    for (int g = 0; g < 2; g++) {
        float4 v = *(const float4*)(r + g * 4);
        float x[4] = {v.x, v.y, v.z, v.w};
        uint32_t hi[4], lo[4];
#pragma unroll
        for (int q = 0; q < 4; q++) {
            m2 = fmaf(x[q], x[q], m2);
            ms += x[q];
            hi[q] = tf32u(x[q]);
            lo[q] = tf32u(x[q] - __uint_as_float(hi[q]));
        }
        g_mhi4[row * 64 + lane * 2 + g] = make_uint4(hi[0], hi[1], hi[2], hi[3]);
        g_mlo4[row * 64 + lane * 2 + g] = make_uint4(lo[0], lo[1], lo[2], lo[3]);
    }
#pragma unroll
    for (int off = 16; off; off >>= 1) {
        m2 += __shfl_xor_sync(0xffffffffu, m2, off);
        ms += __shfl_xor_sync(0xffffffffu, ms, off);
    }
    if (lane == 0) { g_m2[row] = m2; g_ms[row] = ms; }
}

__global__ void k_noop() {}

// ---------------- insertion helper ------------------------------------------
__device__ __forceinline__ void ins5(float v, float &t0, float &t1, float &t2,
                                     float &t3, float &t4) {
    if (v < t4) {
        if (v < t3) {
            t4 = t3;
            if (v < t2) {
                t3 = t2;
                if (v < t1) {
                    t2 = t1;
                    if (v < t0) { t1 = t0; t0 = v; } else t1 = v;
                } else t2 = v;
            } else t3 = v;
        } else t4 = v;
    }
}

// ---------------- K1: LEAN tf32-split GEMM + d, cp.async A+B double-buffer ---
// CTA 128x256, 16 warps, warp tile 32x64. K in 8 chunks of 32, 4 k8-steps each.
// Barrier order per chunk: sync (prev mma done) -> issue next -> wait -> sync
// (data visible) -> A split -> sync -> mma. No WAR/RAW hazards on stage reuse.
#define LDS_A 36
#define TILE_LD 260
#define SA_RAW 0                       /* 2 stages x 18432 */
#define SA_HI 36864
#define SA_LO 55296
#define SB_BASE 73728                  /* stage s hi: +s*73728; lo: +36864 */
#define SB_STAGE 73728
#define ST_M2 221184
#define ST_MS 222208
#define ST_Z2 223232
#define ST_ZS 223744
#define GSMEM_TOTAL 224256

__device__ __forceinline__ void issue_AB(uint32_t sb, const float* z,
                                         int rowBase, int c, int t) {
    // raw A: 128 rows x 8 quads = 1024 quads; 512 threads -> 2 each
    uint32_t araw = sb + SA_RAW + (uint32_t)(c & 1) * 18432;
#pragma unroll
    for (int i = 0; i < 2; i++) {
        int e = t + 512 * i;             // 0..1023
        int row = e >> 3, q = e & 7;
        cpa16(araw + ((uint32_t)row * LDS_A + q * 4) * 4,
              z + (size_t)(rowBase + row) * DH + c * 32 + q * 4);
    }
    // B: 256 rows x 8 quads per half = 2048 quads; 512 threads -> 4 each
    uint32_t bbase = sb + SB_BASE + (uint32_t)(c & 1) * SB_STAGE;
#pragma unroll
    for (int i = 0; i < 4; i++) {
        int e = t + 512 * i;             // 0..2047
        int row = e >> 3, q = e & 7;
        uint32_t off = ((uint32_t)row * LDS_A + q * 4) * 4;
        cpa16(bbase + off, &g_mhi4[row * 64 + c * 8 + q]);
        cpa16(bbase + SB_STAGE / 2 + off, &g_mlo4[row * 64 + c * 8 + q]);
    }
    asm volatile("cp.async.commit_group;");
}

__global__ __launch_bounds__(512, 1) void k_gemm(const float* __restrict__ z) {
    extern __shared__ char smem[];
    const uint32_t sb = smem_u32(smem);
    const int t = threadIdx.x;
    const int wid = t >> 5, lane = t & 31;
    const int wr = wid >> 2, wc = wid & 3;
    const int rowBase = blockIdx.x * 128;

    float* s_m2 = (float*)(smem + ST_M2);
    float* s_ms = (float*)(smem + ST_MS);
    float* s_z2 = (float*)(smem + ST_Z2);
    float* s_zs = (float*)(smem + ST_ZS);
    if (t < 256) { s_m2[t] = g_m2[t]; s_ms[t] = g_ms[t]; }

    float acc[2][8][4];
#pragma unroll
    for (int mt = 0; mt < 2; mt++)
#pragma unroll
        for (int j = 0; j < 8; j++)
#pragma unroll
            for (int q = 0; q < 4; q++) acc[mt][j][q] = 0.f;

    const int ar = t >> 2, aq = t & 3;
    float z2p = 0.f, zsp = 0.f;

    const uint32_t a_off = ((uint32_t)(wr * 32 + (lane & 15)) * LDS_A +
                            ((lane >> 4) << 2)) * 4;
    const uint32_t b_off = ((uint32_t)(wc * 64 + ((lane >> 4) << 3) + (lane & 7)) * LDS_A +
                            ((lane & 8) >> 1)) * 4;

    // prologue: prefetch chunk 0 (A raw + B) into stage 0
    issue_AB(sb, z, rowBase, 0, t);

#pragma unroll 1
    for (int c = 0; c < 8; c++) {
        __syncthreads();   // all warps done with chunk c-1 mma: stages reusable
        if (c < 7) {
            issue_AB(sb, z, rowBase, c + 1, t);
            asm volatile("cp.async.wait_group 1;");  // chunk c landed
        } else {
            asm volatile("cp.async.wait_group 0;");
        }
        __syncthreads();   // chunk c data visible block-wide

        // ---- A: split raw smem -> hi/lo tf32 (no global latency) -------------
        {
            const float* rawp = (const float*)(smem + SA_RAW + (c & 1) * 18432);
            uint32_t roff = (uint32_t)ar * LDS_A + aq * 8;
            float4 v0 = *(const float4*)(rawp + roff);
            float4 v1 = *(const float4*)(rawp + roff + 4);
            float xs[8] = {v0.x, v0.y, v0.z, v0.w, v1.x, v1.y, v1.z, v1.w};
            float hi[8], lo[8];
#pragma unroll
            for (int q = 0; q < 8; q++) {
                z2p = fmaf(xs[q], xs[q], z2p);
                zsp += xs[q];
                uint32_t h = tf32u(xs[q]);
                hi[q] = __uint_as_float(h);
                lo[q] = __uint_as_float(tf32u(xs[q] - hi[q]));
            }
            uint32_t off = ((uint32_t)ar * LDS_A + aq * 8) * 4;
            *(float4*)(smem + SA_HI + off)      = make_float4(hi[0], hi[1], hi[2], hi[3]);
            *(float4*)(smem + SA_HI + off + 16) = make_float4(hi[4], hi[5], hi[6], hi[7]);
            *(float4*)(smem + SA_LO + off)      = make_float4(lo[0], lo[1], lo[2], lo[3]);
            *(float4*)(smem + SA_LO + off + 16) = make_float4(lo[4], lo[5], lo[6], lo[7]);
        }
        __syncthreads();   // split A visible

        const uint32_t bh_base = sb + SB_BASE + (c & 1) * SB_STAGE;
        const uint32_t bl_base = bh_base + SB_STAGE / 2;

        // ---- mma over 4 k8-steps, full-width passes --------------------------
#pragma unroll
        for (int ks = 0; ks < 4; ks++) {
            const uint32_t kb = (uint32_t)ks * 32;
            uint32_t ah[2][4], al[2][4];
            ldmx4(ah[0], sb + SA_HI + a_off + kb);
            ldmx4(ah[1], sb + SA_HI + a_off + kb + 16 * LDS_A * 4);
            ldmx4(al[0], sb + SA_LO + a_off + kb);
            ldmx4(al[1], sb + SA_LO + a_off + kb + 16 * LDS_A * 4);

            uint32_t bh[4][4];
#pragma unroll
            for (int p = 0; p < 4; p++)
                ldmx4(bh[p], bh_base + b_off + kb + (uint32_t)p * 16 * LDS_A * 4);
#pragma unroll
            for (int p = 0; p < 4; p++) {
                mma_tf32(acc[0][2 * p],     ah[0], &bh[p][0]);
                mma_tf32(acc[0][2 * p + 1], ah[0], &bh[p][2]);
                mma_tf32(acc[1][2 * p],     ah[1], &bh[p][0]);
                mma_tf32(acc[1][2 * p + 1], ah[1], &bh[p][2]);
            }
#pragma unroll
            for (int p = 0; p < 4; p++) {
                mma_tf32(acc[0][2 * p],     al[0], &bh[p][0]);
                mma_tf32(acc[0][2 * p + 1], al[0], &bh[p][2]);
                mma_tf32(acc[1][2 * p],     al[1], &bh[p][0]);
                mma_tf32(acc[1][2 * p + 1], al[1], &bh[p][2]);
            }
            uint32_t bl[4][4];
#pragma unroll
            for (int p = 0; p < 4; p++)
                ldmx4(bl[p], bl_base + b_off + kb + (uint32_t)p * 16 * LDS_A * 4);
#pragma unroll
            for (int p = 0; p < 4; p++) {
                mma_tf32(acc[0][2 * p],     ah[0], &bl[p][0]);
                mma_tf32(acc[0][2 * p + 1], ah[0], &bl[p][2]);
                mma_tf32(acc[1][2 * p],     ah[1], &bl[p][0]);
                mma_tf32(acc[1][2 * p + 1], ah[1], &bl[p][2]);
            }
        }
    }

    z2p += __shfl_xor_sync(0xffffffffu, z2p, 1);
    z2p += __shfl_xor_sync(0xffffffffu, z2p, 2);
    zsp += __shfl_xor_sync(0xffffffffu, zsp, 1);
    zsp += __shfl_xor_sync(0xffffffffu, zsp, 2);
    if (aq == 0) { s_z2[ar] = z2p; s_zs[ar] = zsp; }
    __syncthreads();

    float* tile = (float*)smem;
    const float cterm = (float)DH * EPSV * EPSV;
#pragma unroll
    for (int mt = 0; mt < 2; mt++) {
        const int r0 = wr * 32 + mt * 16 + (lane >> 2);
        const float z2va = s_z2[r0], zsva = s_zs[r0];
        const float z2vb = s_z2[r0 + 8], zsvb = s_zs[r0 + 8];
#pragma unroll
        for (int nt = 0; nt < 8; nt++) {
            const int c0 = wc * 64 + nt * 8 + (lane & 3) * 2;
            float m20 = s_m2[c0], ms0 = s_ms[c0];
            float m21 = s_m2[c0 + 1], ms1 = s_ms[c0 + 1];
            float d00 = z2va + m20 - 2.f * acc[mt][nt][0] + 2.f * EPSV * (zsva - ms0) + cterm;
            float d01 = z2va + m21 - 2.f * acc[mt][nt][1] + 2.f * EPSV * (zsva - ms1) + cterm;
            float d10 = z2vb + m20 - 2.f * acc[mt][nt][2] + 2.f * EPSV * (zsvb - ms0) + cterm;
            float d11 = z2vb + m21 - 2.f * acc[mt][nt][3] + 2.f * EPSV * (zsvb - ms1) + cterm;
            tile[r0 * TILE_LD + c0]           = sqrtf(fmaxf(d00, 0.f));
            tile[r0 * TILE_LD + c0 + 1]       = sqrtf(fmaxf(d01, 0.f));
            tile[(r0 + 8) * TILE_LD + c0]     = sqrtf(fmaxf(d10, 0.f));
            tile[(r0 + 8) * TILE_LD + c0 + 1] = sqrtf(fmaxf(d11, 0.f));
        }
    }
    __syncthreads();

#pragma unroll
    for (int i = 0; i < 16; i++) {
        int e = t + 512 * i;
        int row = e >> 6, c4 = e & 63;
        float4 v = *(const float4*)&tile[row * TILE_LD + c4 * 4];
        *(float4*)&g_d[(size_t)(rowBase + row) * KC + c4 * 4] = v;
    }
}

// ---------------- K2: top-5 reductions over g_d (row + column partials) ------
__global__ __launch_bounds__(256) void k_top() {
    const int rowBase = blockIdx.x * 128;
    const int t = threadIdx.x;
    const int w = t >> 5, lane = t & 31;

#pragma unroll 1
    for (int rr = 0; rr < 16; rr++) {
        int row = rowBase + w * 16 + rr;
        const float* dr = g_d + (size_t)row * KC;
        float4 d0 = *(const float4*)(dr + lane * 4);
        float4 d1 = *(const float4*)(dr + 128 + lane * 4);
        float t0 = INF_F, t1 = INF_F, t2 = INF_F, t3 = INF_F, t4 = INF_F;
        ins5(d0.x, t0, t1, t2, t3, t4); ins5(d0.y, t0, t1, t2, t3, t4);
        ins5(d0.z, t0, t1, t2, t3, t4); ins5(d0.w, t0, t1, t2, t3, t4);
        ins5(d1.x, t0, t1, t2, t3, t4); ins5(d1.y, t0, t1, t2, t3, t4);
        ins5(d1.z, t0, t1, t2, t3, t4); ins5(d1.w, t0, t1, t2, t3, t4);
#pragma unroll
        for (int off = 16; off; off >>= 1) {
            float o0 = __shfl_xor_sync(0xffffffffu, t0, off);
            float o1 = __shfl_xor_sync(0xffffffffu, t1, off);
            float o2 = __shfl_xor_sync(0xffffffffu, t2, off);
            float o3 = __shfl_xor_sync(0xffffffffu, t3, off);
            float o4 = __shfl_xor_sync(0xffffffffu, t4, off);
            ins5(o0, t0, t1, t2, t3, t4);
            ins5(o1, t0, t1, t2, t3, t4);
            ins5(o2, t0, t1, t2, t3, t4);
            ins5(o3, t0, t1, t2, t3, t4);
            ins5(o4, t0, t1, t2, t3, t4);
        }
        if (lane == 0) {
            float* rp = g_relz + (size_t)row * 5;
            rp[0] = t0; rp[1] = t1; rp[2] = t2; rp[3] = t3; rp[4] = t4;
        }
    }

    {
        float t0 = INF_F, t1 = INF_F, t2 = INF_F, t3 = INF_F, t4 = INF_F;
        const float* p = g_d + (size_t)rowBase * KC + t;
#pragma unroll 8
        for (int r = 0; r < 128; r++)
            ins5(p[(size_t)r * KC], t0, t1, t2, t3, t4);
        float* pp = g_part1 + (size_t)blockIdx.x * 5 * KC + t;
        pp[0 * KC] = t0; pp[1 * KC] = t1; pp[2 * KC] = t2;
        pp[3 * KC] = t3; pp[4 * KC] = t4;
    }
}

// ---------------- bisection (mirrors reference update rule) -----------------
__device__ __forceinline__ float calibrate(float a1, float a2, float a3, float a4,
                                           float target) {
    float mid0 = 0.f, mid1 = SIGMA_HI_V, sigma = 1.f;
#pragma unroll 1
    for (int it = 0; it < CAL_ITERS; it++) {
        float inv = __frcp_rn(sigma);
        float cur = 1.f + __expf(-a1 * inv) + __expf(-a2 * inv) +
                    __expf(-a3 * inv) + __expf(-a4 * inv);
        if (cur > target) mid1 = sigma; else mid0 = sigma;
        sigma = 0.5f * (mid0 + mid1);
    }
    return sigma;
}

// ---------------- K3: fused reductions ---------------------------------------
__global__ __launch_bounds__(256) void k_reduce() {
    int b = blockIdx.x;
    if (b < 32) {
        int w = threadIdx.x >> 5, lane = threadIdx.x & 31;
        int col = b * 8 + w;
        float t0 = INF_F, t1 = INF_F, t2 = INF_F, t3 = INF_F, t4 = INF_F;
        for (int p = lane; p < NPART; p += 32) {
            const float* pp = g_part1 + (size_t)p * 5 * KC + col;
#pragma unroll
            for (int s = 0; s < 5; s++) ins5(pp[s * KC], t0, t1, t2, t3, t4);
        }
#pragma unroll
        for (int off = 16; off; off >>= 1) {
            float o0 = __shfl_xor_sync(0xffffffffu, t0, off);
            float o1 = __shfl_xor_sync(0xffffffffu, t1, off);
            float o2 = __shfl_xor_sync(0xffffffffu, t2, off);
            float o3 = __shfl_xor_sync(0xffffffffu, t3, off);
            float o4 = __shfl_xor_sync(0xffffffffu, t4, off);
            ins5(o0, t0, t1, t2, t3, t4);
            ins5(o1, t0, t1, t2, t3, t4);
            ins5(o2, t0, t1, t2, t3, t4);
            ins5(o3, t0, t1, t2, t3, t4);
            ins5(o4, t0, t1, t2, t3, t4);
        }
        if (lane == 0) {
            float rho = t0;
            g_rhou[col] = rho;
            g_colsum[col] = 0.f;
            float a1 = fmaxf(t1 - rho, 0.f), a2 = fmaxf(t2 - rho, 0.f);
            float a3 = fmaxf(t3 - rho, 0.f), a4 = fmaxf(t4 - rho, 0.f);
            g_sigu[col] = calibrate(a1, a2, a3, a4, TARGET_U);
        }
    } else {
        int row = (b - 32) * 256 + threadIdx.x;
        const float* r = g_relz + (size_t)row * 5;
        float rho = r[0];
        float a1 = fmaxf(r[1] - rho, 0.f), a2 = fmaxf(r[2] - rho, 0.f);
        float a3 = fmaxf(r[3] - rho, 0.f), a4 = fmaxf(r[4] - rho, 0.f);
        g_rhoz[row] = rho;
        g_sigz[row] = calibrate(a1, a2, a3, a4, TARGET_Z);
    }
}

// ---------------- K4: W1 / W2 / S + colsum (warp per row, float4 I/O) --------
__global__ __launch_bounds__(256) void k_ws(float* __restrict__ out) {
    __shared__ float s_rho[KC], s_isu[KC], s_cs[KC];
    int t = threadIdx.x;
    s_rho[t] = g_rhou[t];
    s_isu[t] = 1.0f / g_sigu[t];
    s_cs[t] = 0.f;
    __syncthreads();

    int lane = t & 31;
    int w = t >> 5;
    int wid = (blockIdx.x << 3) + w;
    const int wstride = gridDim.x << 3;
    const int c0 = lane * 4, c1 = 128 + lane * 4;
    float* outW1a = out;
    float* outS   = out + NKSZ;
    float* outW1b = out + 2 * NKSZ;

    float ru[8], iu[8];
#pragma unroll
    for (int j = 0; j < 4; j++) {
        ru[j] = s_rho[c0 + j];     iu[j] = s_isu[c0 + j];
        ru[4 + j] = s_rho[c1 + j]; iu[4 + j] = s_isu[c1 + j];
    }
    float cs[8];
#pragma unroll
    for (int j = 0; j < 8; j++) cs[j] = 0.f;

    for (int row = wid; row < NROWS; row += wstride) {
        float rho = g_rhoz[row];
        float isz = 1.0f / g_sigz[row];
        const float* dr = g_d + (size_t)row * KC;
        float4 d0 = *(const float4*)(dr + c0);
        float4 d1 = *(const float4*)(dr + c1);
        float dv[8] = {d0.x, d0.y, d0.z, d0.w, d1.x, d1.y, d1.z, d1.w};
        float w1v[8], sv[8];
        float sum = 0.f;
#pragma unroll
        for (int j = 0; j < 8; j++) {
            float w1 = __expf(-fmaxf(dv[j] - rho, 0.f) * isz);
            float w2 = __expf(-fmaxf(dv[j] - ru[j], 0.f) * iu[j]);
            float s = w1 + w2 - w1 * w2;
            w1v[j] = w1; sv[j] = s; sum += s;
        }
#pragma unroll
        for (int off = 16; off; off >>= 1) sum += __shfl_xor_sync(0xffffffffu, sum, off);
        float rinv = 1.0f / sum;
        float4 w1a = make_float4(w1v[0], w1v[1], w1v[2], w1v[3]);
        float4 w1b = make_float4(w1v[4], w1v[5], w1v[6], w1v[7]);
        float4 s0 = make_float4(sv[0] * rinv, sv[1] * rinv, sv[2] * rinv, sv[3] * rinv);
        float4 s1 = make_float4(sv[4] * rinv, sv[5] * rinv, sv[6] * rinv, sv[7] * rinv);
        size_t base = (size_t)row * KC;
        *(float4*)(outW1a + base + c0) = w1a;
        *(float4*)(outW1a + base + c1) = w1b;
        *(float4*)(outW1b + base + c0) = w1a;
        *(float4*)(outW1b + base + c1) = w1b;
        *(float4*)(outS + base + c0) = s0;
        *(float4*)(outS + base + c1) = s1;
        cs[0] += s0.x; cs[1] += s0.y; cs[2] += s0.z; cs[3] += s0.w;
        cs[4] += s1.x; cs[5] += s1.y; cs[6] += s1.z; cs[7] += s1.w;
    }
#pragma unroll
    for (int j = 0; j < 4; j++) {
        atomicAdd(&s_cs[c0 + j], cs[j]);
        atomicAdd(&s_cs[c1 + j], cs[4 + j]);
    }
    __syncthreads();
    atomicAdd(&g_colsum[t], s_cs[t]);
}

// ---------------- K5: Dmat (float4 I/O) ---------------------------------------
__global__ __launch_bounds__(256) void k_dmat(float* __restrict__ out) {
    __shared__ float s_ic[KC];
    int t = threadIdx.x;
    s_ic[t] = 1.0f / g_colsum[t];
    __syncthreads();

    const float* Sm = out + NKSZ;
    float* Dm = out + 3 * NKSZ;
    int lane = t & 31;
    int w = t >> 5;
    int wid = (blockIdx.x << 3) + w;
    const int wstride = gridDim.x << 3;
    const int c0 = lane * 4, c1 = 128 + lane * 4;

    float ic[8];
#pragma unroll
    for (int j = 0; j < 4; j++) {
        ic[j] = s_ic[c0 + j];
        ic[4 + j] = s_ic[c1 + j];
    }

    for (int row = wid; row < NROWS; row += wstride) {
        const float* sr = Sm + (size_t)row * KC;
        float4 v0 = *(const float4*)(sr + c0);
        float4 v1 = *(const float4*)(sr + c1);
        float sv[8] = {v0.x, v0.y, v0.z, v0.w, v1.x, v1.y, v1.z, v1.w};
        float tv[8];
        float sum = 0.f;
#pragma unroll
        for (int j = 0; j < 8; j++) {
            float q = sv[j] * sv[j] * ic[j];
            tv[j] = q; sum += q;
        }
#pragma unroll
        for (int off = 16; off; off >>= 1) sum += __shfl_xor_sync(0xffffffffu, sum, off);
        float rinv = 1.0f / sum;
        float4 o0 = make_float4(tv[0] * rinv, tv[1] * rinv, tv[2] * rinv, tv[3] * rinv);
        float4 o1 = make_float4(tv[4] * rinv, tv[5] * rinv, tv[6] * rinv, tv[7] * rinv);
        size_t base = (size_t)row * KC;
        *(float4*)(Dm + base + c0) = o0;
        *(float4*)(Dm + base + c1) = o1;
    }
}

// ---------------- launcher ---------------------------------------------------
extern "C" void kernel_launch(void* const* d_in, const int* in_sizes, int n_in,
                              void* d_out, int out_size) {
    (void)in_sizes; (void)n_in; (void)out_size;
    const float* z  = (const float*)d_in[0];
    const float* mu = (const float*)d_in[1];
    float* out = (float*)d_out;

    cudaFuncSetAttribute(k_gemm, cudaFuncAttributeMaxDynamicSharedMemorySize,
                         GSMEM_TOTAL);

    k_prep_mu<<<32, 256>>>(mu);                      // #1
    k_noop<<<1, 32>>>();                             // #2
    k_noop<<<1, 32>>>();                             // #3
    k_gemm<<<NROWS / 128, 512, GSMEM_TOTAL>>>(z);    // #4 <- ncu slot
    k_top<<<NROWS / 128, 256>>>();                   // #5
    k_reduce<<<288, 256>>>();                        // #6
    k_ws<<<1024, 256>>>(out);                        // #7
    k_dmat<<<1024, 256>>>(out);                      // #8
}